// round 1
// baseline (speedup 1.0000x reference)
#include <cuda_runtime.h>

#define N0_   292864
#define N1_   11264
#define N2_   1024
#define F0_   25
#define F1_   10
#define D_IN_ 256
#define HID_  256
#define NCLS_ 47
#define KCAT_ 512   // concat [self | neighbor-mean]

// ---------------- scratch (device globals; no allocation allowed) ----------
__device__ float g_Acat0[N1_ * KCAT_];   // 23 MB: [x_dst | agg0]
__device__ float g_Bcat0[KCAT_ * HID_];  // [W_self0 ; W_neigh0]
__device__ float g_H[N1_ * HID_];        // relu(layer0)
__device__ float g_Acat1[N2_ * KCAT_];   // [h_dst | agg1]
__device__ float g_Bcat1[KCAT_ * NCLS_]; // [W_self1 ; W_neigh1]

// ---------------- build stacked weight matrices ----------------------------
__global__ void prep_b_kernel(const float* __restrict__ Ws0,
                              const float* __restrict__ Wn0,
                              const float* __restrict__ Ws1,
                              const float* __restrict__ Wn1) {
    int idx = blockIdx.x * blockDim.x + threadIdx.x;
    if (idx < KCAT_ * HID_) {
        int k = idx / HID_, n = idx % HID_;
        g_Bcat0[idx] = (k < D_IN_) ? Ws0[k * HID_ + n] : Wn0[(k - D_IN_) * HID_ + n];
    }
    if (idx < KCAT_ * NCLS_) {
        int k = idx / NCLS_, n = idx % NCLS_;
        g_Bcat1[idx] = (k < HID_) ? Ws1[k * NCLS_ + n] : Wn1[(k - HID_) * NCLS_ + n];
    }
}

// ---------------- layer-0 gather + neighbor mean ----------------------------
// One block per dst row; thread t owns feature column t. 26 coalesced 1KB row
// reads per block; 25-way unrolled loop => high MLP per thread.
__global__ __launch_bounds__(256) void gather0_kernel(
    const int* __restrict__ gids0,
    const int* __restrict__ nbr0,
    const float* __restrict__ emb) {
    int i = blockIdx.x;
    int t = threadIdx.x;

    __shared__ int sg[F0_];
    if (t < F0_) {
        int n = nbr0[i * F0_ + t];
        sg[t] = gids0[n];
    }
    __syncthreads();

    int gd = gids0[i];
    float xdst = emb[(size_t)gd * D_IN_ + t];

    float acc = 0.f;
#pragma unroll
    for (int j = 0; j < F0_; j++) {
        acc += emb[(size_t)sg[j] * D_IN_ + t];
    }

    g_Acat0[i * KCAT_ + t]          = xdst;
    g_Acat0[i * KCAT_ + D_IN_ + t]  = acc * (1.0f / F0_);
}

// ---------------- layer-0 GEMM: H = relu(Acat0 @ Bcat0 + b0) ---------------
// 128x128 tile, BK=16, 256 threads, 8x8 microtile, A stored k-major in smem.
#define BM 128
#define BN 128
#define BK 16

__global__ __launch_bounds__(256) void gemm0_kernel(const float* __restrict__ b0) {
    __shared__ float As[BK][BM];
    __shared__ float Bs[BK][BN];

    const int bm = blockIdx.x * BM;   // gridDim.x = 88
    const int bn = blockIdx.y * BN;   // gridDim.y = 2
    const int tid = threadIdx.x;
    const int tm = (tid / 16) * 8;
    const int tn = (tid % 16) * 8;

    float acc[8][8];
#pragma unroll
    for (int y = 0; y < 8; y++)
#pragma unroll
        for (int x = 0; x < 8; x++) acc[y][x] = 0.f;

    const float* A = g_Acat0;  // M x KCAT
    const float* B = g_Bcat0;  // KCAT x HID

    for (int k0 = 0; k0 < KCAT_; k0 += BK) {
        // A tile: 128 rows x 16 k, transposed into As[k][m]
#pragma unroll
        for (int r = 0; r < 2; r++) {
            int f   = tid * 2 + r;
            int row = f >> 2;          // 0..127
            int c4  = (f & 3) * 4;     // 0,4,8,12
            float4 v = *(const float4*)&A[(size_t)(bm + row) * KCAT_ + k0 + c4];
            As[c4 + 0][row] = v.x;
            As[c4 + 1][row] = v.y;
            As[c4 + 2][row] = v.z;
            As[c4 + 3][row] = v.w;
        }
        // B tile: 16 k x 128 n, direct copy
#pragma unroll
        for (int r = 0; r < 2; r++) {
            int f   = tid * 2 + r;
            int row = f >> 5;          // 0..15
            int c   = (f & 31) * 4;    // 0..124
            *(float4*)&Bs[row][c] =
                *(const float4*)&B[(size_t)(k0 + row) * HID_ + bn + c];
        }
        __syncthreads();

#pragma unroll
        for (int k = 0; k < BK; k++) {
            float a[8], bb[8];
            *(float4*)&a[0]  = *(float4*)&As[k][tm];
            *(float4*)&a[4]  = *(float4*)&As[k][tm + 4];
            *(float4*)&bb[0] = *(float4*)&Bs[k][tn];
            *(float4*)&bb[4] = *(float4*)&Bs[k][tn + 4];
#pragma unroll
            for (int y = 0; y < 8; y++)
#pragma unroll
                for (int x = 0; x < 8; x++) acc[y][x] += a[y] * bb[x];
        }
        __syncthreads();
    }

    // bias + relu + store H
#pragma unroll
    for (int y = 0; y < 8; y++) {
        int m = bm + tm + y;
#pragma unroll
        for (int x = 0; x < 8; x += 4) {
            float4 o;
            o.x = fmaxf(acc[y][x + 0] + b0[bn + tn + x + 0], 0.f);
            o.y = fmaxf(acc[y][x + 1] + b0[bn + tn + x + 1], 0.f);
            o.z = fmaxf(acc[y][x + 2] + b0[bn + tn + x + 2], 0.f);
            o.w = fmaxf(acc[y][x + 3] + b0[bn + tn + x + 3], 0.f);
            *(float4*)&g_H[(size_t)m * HID_ + bn + tn + x] = o;
        }
    }
}

// ---------------- layer-1 gather + neighbor mean ----------------------------
__global__ __launch_bounds__(256) void gather1_kernel(const int* __restrict__ nbr1) {
    int i = blockIdx.x;
    int t = threadIdx.x;

    __shared__ int sn[F1_];
    if (t < F1_) sn[t] = nbr1[i * F1_ + t];
    __syncthreads();

    float acc = 0.f;
#pragma unroll
    for (int j = 0; j < F1_; j++) acc += g_H[(size_t)sn[j] * HID_ + t];

    g_Acat1[i * KCAT_ + t]         = g_H[(size_t)i * HID_ + t];
    g_Acat1[i * KCAT_ + HID_ + t]  = acc * (1.0f / F1_);
}

// ---------------- layer-1 GEMM: out = Acat1 @ Bcat1 + b1 -------------------
// Thread per (row, class). K=512, B matrix is 96KB => lives in L2/L1.
__global__ __launch_bounds__(256) void out_kernel(const float* __restrict__ b1,
                                                  float* __restrict__ out) {
    int idx = blockIdx.x * blockDim.x + threadIdx.x;
    if (idx >= N2_ * NCLS_) return;
    int i = idx / NCLS_;
    int c = idx % NCLS_;

    const float* a = &g_Acat1[(size_t)i * KCAT_];
    float acc = b1[c];
#pragma unroll 8
    for (int k = 0; k < KCAT_; k++) {
        acc += a[k] * g_Bcat1[k * NCLS_ + c];
    }
    out[idx] = acc;
}

// ---------------- launch ----------------------------------------------------
extern "C" void kernel_launch(void* const* d_in, const int* in_sizes, int n_in,
                              void* d_out, int out_size) {
    const int*   gids0 = (const int*)d_in[0];
    const int*   nbr0  = (const int*)d_in[1];
    const int*   nbr1  = (const int*)d_in[2];
    const float* emb   = (const float*)d_in[3];
    const float* Ws0   = (const float*)d_in[4];
    const float* Wn0   = (const float*)d_in[5];
    const float* b0    = (const float*)d_in[6];
    const float* Ws1   = (const float*)d_in[7];
    const float* Wn1   = (const float*)d_in[8];
    const float* b1    = (const float*)d_in[9];
    float* out = (float*)d_out;

    prep_b_kernel<<<(KCAT_ * HID_ + 255) / 256, 256>>>(Ws0, Wn0, Ws1, Wn1);
    gather0_kernel<<<N1_, 256>>>(gids0, nbr0, emb);
    gemm0_kernel<<<dim3(N1_ / BM, HID_ / BN), 256>>>(b0);
    gather1_kernel<<<N2_, 256>>>(nbr1);
    out_kernel<<<(N2_ * NCLS_ + 255) / 256, 256>>>(b1, out);
}

// round 5
// speedup vs baseline: 1.4550x; 1.4550x over previous
#include <cuda_runtime.h>
#include <cuda_bf16.h>
#include <cstdint>

#define N0_   292864
#define N1_   11264
#define N2_   1024
#define F0_   25
#define F1_   10
#define D_IN_ 256
#define HID_  256
#define NCLS_ 47
#define KCAT_ 512

// ---------------- scratch (device globals; no allocation allowed) ----------
__device__ __nv_bfloat16 g_Ah[N1_ * KCAT_];    // A hi split, [i][k] row-major
__device__ __nv_bfloat16 g_Al[N1_ * KCAT_];    // A lo split
__device__ __nv_bfloat16 g_Bh[KCAT_ * HID_];   // B hi, [k][n] row-major
__device__ __nv_bfloat16 g_Bl[KCAT_ * HID_];   // B lo
__device__ float g_H[N1_ * HID_];              // relu(layer0), fp32
__device__ float g_Acat1[N2_ * KCAT_];
__device__ float g_Bcat1[KCAT_ * NCLS_];

// ================= helpers =================================================
__device__ __forceinline__ uint32_t smem_u32(const void* p) {
    uint32_t a;
    asm("{ .reg .u64 t; cvta.to.shared.u64 t, %1; cvt.u32.u64 %0, t; }"
        : "=r"(a) : "l"(p));
    return a;
}
__device__ __forceinline__ void cp_async16(uint32_t dst, const void* src) {
    asm volatile("cp.async.cg.shared.global [%0], [%1], 16;"
                 :: "r"(dst), "l"(src) : "memory");
}
#define LDMX4(r, a)                                                            \
    asm volatile("ldmatrix.sync.aligned.m8n8.x4.shared.b16 {%0,%1,%2,%3}, [%4];" \
        : "=r"((r)[0]), "=r"((r)[1]), "=r"((r)[2]), "=r"((r)[3]) : "r"(a))
#define LDMX4T(r, a)                                                           \
    asm volatile("ldmatrix.sync.aligned.m8n8.x4.trans.shared.b16 {%0,%1,%2,%3}, [%4];" \
        : "=r"((r)[0]), "=r"((r)[1]), "=r"((r)[2]), "=r"((r)[3]) : "r"(a))

__device__ __forceinline__ void mma16816(float* c, const uint32_t* a,
                                         uint32_t b0, uint32_t b1) {
    asm volatile(
        "mma.sync.aligned.m16n8k16.row.col.f32.bf16.bf16.f32 "
        "{%0,%1,%2,%3}, {%4,%5,%6,%7}, {%8,%9}, {%0,%1,%2,%3};"
        : "+f"(c[0]), "+f"(c[1]), "+f"(c[2]), "+f"(c[3])
        : "r"(a[0]), "r"(a[1]), "r"(a[2]), "r"(a[3]), "r"(b0), "r"(b1));
}

// ================= weight prep (hi/lo bf16 split, [k][n] layout) ===========
__global__ void prep_b_kernel(const float* __restrict__ Ws0,
                              const float* __restrict__ Wn0,
                              const float* __restrict__ Ws1,
                              const float* __restrict__ Wn1) {
    int idx = blockIdx.x * blockDim.x + threadIdx.x;
    if (idx < KCAT_ * HID_) {
        int k = idx / HID_, n = idx % HID_;
        float w = (k < D_IN_) ? Ws0[k * HID_ + n] : Wn0[(k - D_IN_) * HID_ + n];
        __nv_bfloat16 hi = __float2bfloat16(w);
        __nv_bfloat16 lo = __float2bfloat16(w - __bfloat162float(hi));
        g_Bh[idx] = hi;
        g_Bl[idx] = lo;
    }
    if (idx < KCAT_ * NCLS_) {
        int k = idx / NCLS_, n = idx % NCLS_;
        g_Bcat1[idx] = (k < HID_) ? Ws1[k * NCLS_ + n] : Wn1[(k - HID_) * NCLS_ + n];
    }
}

// ================= layer-0 gather + mean -> bf16 hi/lo ======================
__global__ __launch_bounds__(256) void gather0_kernel(
    const int* __restrict__ gids0,
    const int* __restrict__ nbr0,
    const float* __restrict__ emb) {
    int i = blockIdx.x;
    int t = threadIdx.x;

    __shared__ int sg[F0_];
    if (t < F0_) sg[t] = gids0[nbr0[i * F0_ + t]];
    __syncthreads();

    float xdst = emb[(size_t)gids0[i] * D_IN_ + t];

    float acc = 0.f;
#pragma unroll
    for (int j = 0; j < F0_; j++) acc += emb[(size_t)sg[j] * D_IN_ + t];
    acc *= (1.0f / F0_);

    __nv_bfloat16 h0 = __float2bfloat16(xdst);
    __nv_bfloat16 l0 = __float2bfloat16(xdst - __bfloat162float(h0));
    __nv_bfloat16 h1 = __float2bfloat16(acc);
    __nv_bfloat16 l1 = __float2bfloat16(acc - __bfloat162float(h1));

    size_t base = (size_t)i * KCAT_;
    g_Ah[base + t] = h0;          g_Al[base + t] = l0;
    g_Ah[base + D_IN_ + t] = h1;  g_Al[base + D_IN_ + t] = l1;
}

// ================= layer-0 GEMM via mma.sync bf16 (3-term split) ===========
// H = relu([x|agg] @ [Ws;Wn] + b0)
// CTA tile 128x128, K-chunk 64, 2-stage cp.async pipeline, 8 warps (64x32 each)
// 24 logical K-chunks = 3 passes (AhBh, AhBl, AlBh) x 8 chunks of K=512.
#define SM_ASTAGE 16384
#define SM_BOFF   32768
#define SM_TOTAL  65536

__device__ __forceinline__ void load_chunk(uint32_t sb, int buf,
                                           const __nv_bfloat16* Ag,
                                           const __nv_bfloat16* Bg,
                                           int bm, int bn, int kc, int tid) {
    uint32_t As = sb + buf * SM_ASTAGE;
    uint32_t Bs = sb + SM_BOFF + buf * SM_ASTAGE;
    // A tile: 128 rows x 64 k (128B per row), swizzled
#pragma unroll
    for (int i = 0; i < 4; i++) {
        int idx = tid + i * 256;
        int row = idx >> 3, c16 = idx & 7;
        const char* src = (const char*)Ag + (size_t)(bm + row) * (KCAT_ * 2)
                        + kc * 128 + c16 * 16;
        uint32_t dst = As + row * 128 + ((c16 ^ (row & 7)) * 16);
        cp_async16(dst, src);
    }
    // B tile: 64 k-rows x 128 n (256B per row, two 128B swizzle atoms)
#pragma unroll
    for (int i = 0; i < 4; i++) {
        int idx = tid + i * 256;
        int k = idx >> 4, c = idx & 15;
        const char* src = (const char*)Bg + (size_t)(kc * 64 + k) * (HID_ * 2)
                        + bn * 2 + c * 16;
        uint32_t dst = Bs + k * 256 + (c >> 3) * 128 + (((c & 7) ^ (k & 7)) * 16);
        cp_async16(dst, src);
    }
    asm volatile("cp.async.commit_group;" ::: "memory");
}

__device__ __forceinline__ void compute_chunk(uint32_t sb, int buf, int wm,
                                              int wn, int lane,
                                              float acc[4][4][4]) {
    uint32_t As = sb + buf * SM_ASTAGE;
    uint32_t Bs = sb + SM_BOFF + buf * SM_ASTAGE;
#pragma unroll
    for (int step = 0; step < 4; step++) {
        uint32_t a[4][4], b[2][4];
#pragma unroll
        for (int mi = 0; mi < 4; mi++) {
            int row = wm + mi * 16 + (lane & 15);
            int c16 = 2 * step + (lane >> 4);
            LDMX4(a[mi], As + row * 128 + ((c16 ^ (row & 7)) * 16));
        }
#pragma unroll
        for (int nb = 0; nb < 2; nb++) {
            int k  = step * 16 + (lane & 15);
            int cg = ((wn + nb * 16) >> 3) + (lane >> 4);  // global c16, 0..15
            LDMX4T(b[nb], Bs + k * 256 + (cg >> 3) * 128
                         + (((cg & 7) ^ (k & 7)) * 16));
        }
#pragma unroll
        for (int mi = 0; mi < 4; mi++)
#pragma unroll
            for (int ni = 0; ni < 4; ni++)
                mma16816(acc[mi][ni], a[mi],
                         b[ni >> 1][(ni & 1) * 2],
                         b[ni >> 1][(ni & 1) * 2 + 1]);
    }
}

__global__ __launch_bounds__(256) void gemm0_mma_kernel(const float* __restrict__ b0) {
    extern __shared__ char smem[];
    const uint32_t sb = smem_u32(smem);
    const int tid  = threadIdx.x;
    const int lane = tid & 31;
    const int warp = tid >> 5;
    const int wm = (warp & 1) * 64;
    const int wn = (warp >> 1) * 32;
    const int bm = blockIdx.x * 128;
    const int bn = blockIdx.y * 128;

    float acc[4][4][4];
#pragma unroll
    for (int i = 0; i < 4; i++)
#pragma unroll
        for (int j = 0; j < 4; j++)
#pragma unroll
            for (int q = 0; q < 4; q++) acc[i][j][q] = 0.f;

    const int NCH = 24;  // 3 passes x 8 chunks
    load_chunk(sb, 0, g_Ah, g_Bh, bm, bn, 0, tid);
    load_chunk(sb, 1, g_Ah, g_Bh, bm, bn, 1, tid);

#pragma unroll 1
    for (int cc = 0; cc < NCH; cc++) {
        if (cc + 1 < NCH) asm volatile("cp.async.wait_group 1;" ::: "memory");
        else              asm volatile("cp.async.wait_group 0;" ::: "memory");
        __syncthreads();
        compute_chunk(sb, cc & 1, wm, wn, lane, acc);
        __syncthreads();
        int nc = cc + 2;
        if (nc < NCH) {
            int p = nc >> 3;
            const __nv_bfloat16* Ag = (p == 2) ? g_Al : g_Ah;
            const __nv_bfloat16* Bg = (p == 1) ? g_Bl : g_Bh;
            load_chunk(sb, cc & 1, Ag, Bg, bm, bn, nc & 7, tid);
        }
    }

    // epilogue: bias + relu -> g_H (fp32)
#pragma unroll
    for (int mi = 0; mi < 4; mi++) {
#pragma unroll
        for (int ni = 0; ni < 4; ni++) {
            int col = bn + wn + ni * 8 + (lane & 3) * 2;
            float bx = __ldg(&b0[col]);
            float by = __ldg(&b0[col + 1]);
            int r0 = bm + wm + mi * 16 + (lane >> 2);
            float2 v0, v1;
            v0.x = fmaxf(acc[mi][ni][0] + bx, 0.f);
            v0.y = fmaxf(acc[mi][ni][1] + by, 0.f);
            v1.x = fmaxf(acc[mi][ni][2] + bx, 0.f);
            v1.y = fmaxf(acc[mi][ni][3] + by, 0.f);
            *(float2*)&g_H[(size_t)r0 * HID_ + col]       = v0;
            *(float2*)&g_H[(size_t)(r0 + 8) * HID_ + col] = v1;
        }
    }
}

// ================= layer-1 gather + mean ===================================
__global__ __launch_bounds__(256) void gather1_kernel(const int* __restrict__ nbr1) {
    int i = blockIdx.x;
    int t = threadIdx.x;

    __shared__ int sn[F1_];
    if (t < F1_) sn[t] = nbr1[i * F1_ + t];
    __syncthreads();

    float acc = 0.f;
#pragma unroll
    for (int j = 0; j < F1_; j++) acc += g_H[(size_t)sn[j] * HID_ + t];

    g_Acat1[i * KCAT_ + t]        = g_H[(size_t)i * HID_ + t];
    g_Acat1[i * KCAT_ + HID_ + t] = acc * (1.0f / F1_);
}

// ================= layer-1 GEMM (tiny, fp32 SIMT) ==========================
__global__ __launch_bounds__(256) void out_kernel(const float* __restrict__ b1,
                                                  float* __restrict__ out) {
    int idx = blockIdx.x * blockDim.x + threadIdx.x;
    if (idx >= N2_ * NCLS_) return;
    int i = idx / NCLS_;
    int c = idx % NCLS_;

    const float* a = &g_Acat1[(size_t)i * KCAT_];
    float acc = b1[c];
#pragma unroll 8
    for (int k = 0; k < KCAT_; k++) acc += a[k] * g_Bcat1[k * NCLS_ + c];
    out[idx] = acc;
}

// ================= launch ===================================================
extern "C" void kernel_launch(void* const* d_in, const int* in_sizes, int n_in,
                              void* d_out, int out_size) {
    const int*   gids0 = (const int*)d_in[0];
    const int*   nbr0  = (const int*)d_in[1];
    const int*   nbr1  = (const int*)d_in[2];
    const float* emb   = (const float*)d_in[3];
    const float* Ws0   = (const float*)d_in[4];
    const float* Wn0   = (const float*)d_in[5];
    const float* b0    = (const float*)d_in[6];
    const float* Ws1   = (const float*)d_in[7];
    const float* Wn1   = (const float*)d_in[8];
    const float* b1    = (const float*)d_in[9];
    float* out = (float*)d_out;

    cudaFuncSetAttribute(gemm0_mma_kernel,
                         cudaFuncAttributeMaxDynamicSharedMemorySize, SM_TOTAL);

    prep_b_kernel<<<(KCAT_ * HID_ + 255) / 256, 256>>>(Ws0, Wn0, Ws1, Wn1);
    gather0_kernel<<<N1_, 256>>>(gids0, nbr0, emb);
    gemm0_mma_kernel<<<dim3(N1_ / 128, HID_ / 128), 256, SM_TOTAL>>>(b0);
    gather1_kernel<<<N2_, 256>>>(nbr1);
    out_kernel<<<(N2_ * NCLS_ + 255) / 256, 256>>>(b1, out);
}

// round 6
// speedup vs baseline: 1.8094x; 1.2436x over previous
#include <cuda_runtime.h>
#include <cuda_bf16.h>
#include <cstdint>

#define N0_   292864
#define N1_   11264
#define N2_   1024
#define F0_   25
#define F1_   10
#define D_IN_ 256
#define HID_  256
#define NCLS_ 47
#define KCAT_ 512

// ---------------- scratch (device globals; no allocation allowed) ----------
__device__ __nv_bfloat16 g_Ah[N1_ * KCAT_];    // A hi split (compacted rows)
__device__ __nv_bfloat16 g_Al[N1_ * KCAT_];    // A lo split
__device__ __nv_bfloat16 g_Bh[KCAT_ * HID_];   // B hi, [k][n]
__device__ __nv_bfloat16 g_Bl[KCAT_ * HID_];   // B lo
__device__ float g_H[N1_ * HID_];              // relu(layer0), compacted rows
__device__ float g_Acat1[N2_ * KCAT_];
__device__ float g_Bcat1[KCAT_ * NCLS_];
__device__ int   g_remap[N1_];                 // original row -> compact pos
__device__ int   g_list[N1_];                  // compact pos -> original row
__device__ int   g_cnt[1];                     // # extra rows beyond 1024

// ================= helpers =================================================
__device__ __forceinline__ uint32_t smem_u32(const void* p) {
    uint32_t a;
    asm("{ .reg .u64 t; cvta.to.shared.u64 t, %1; cvt.u32.u64 %0, t; }"
        : "=r"(a) : "l"(p));
    return a;
}
__device__ __forceinline__ void cp_async16(uint32_t dst, const void* src) {
    asm volatile("cp.async.cg.shared.global [%0], [%1], 16;"
                 :: "r"(dst), "l"(src) : "memory");
}
#define LDMX4(r, a)                                                            \
    asm volatile("ldmatrix.sync.aligned.m8n8.x4.shared.b16 {%0,%1,%2,%3}, [%4];" \
        : "=r"((r)[0]), "=r"((r)[1]), "=r"((r)[2]), "=r"((r)[3]) : "r"(a))
#define LDMX4T(r, a)                                                           \
    asm volatile("ldmatrix.sync.aligned.m8n8.x4.trans.shared.b16 {%0,%1,%2,%3}, [%4];" \
        : "=r"((r)[0]), "=r"((r)[1]), "=r"((r)[2]), "=r"((r)[3]) : "r"(a))

__device__ __forceinline__ void mma16816(float* c, const uint32_t* a,
                                         uint32_t b0, uint32_t b1) {
    asm volatile(
        "mma.sync.aligned.m16n8k16.row.col.f32.bf16.bf16.f32 "
        "{%0,%1,%2,%3}, {%4,%5,%6,%7}, {%8,%9}, {%0,%1,%2,%3};"
        : "+f"(c[0]), "+f"(c[1]), "+f"(c[2]), "+f"(c[3])
        : "r"(a[0]), "r"(a[1]), "r"(a[2]), "r"(a[3]), "r"(b0), "r"(b1));
}

// ================= weight prep =============================================
__global__ void prep_b_kernel(const float* __restrict__ Ws0,
                              const float* __restrict__ Wn0,
                              const float* __restrict__ Ws1,
                              const float* __restrict__ Wn1) {
    int idx = blockIdx.x * blockDim.x + threadIdx.x;
    if (idx < KCAT_ * HID_) {
        int k = idx / HID_, n = idx % HID_;
        float w = (k < D_IN_) ? Ws0[k * HID_ + n] : Wn0[(k - D_IN_) * HID_ + n];
        __nv_bfloat16 hi = __float2bfloat16(w);
        __nv_bfloat16 lo = __float2bfloat16(w - __bfloat162float(hi));
        g_Bh[idx] = hi;
        g_Bl[idx] = lo;
    }
    if (idx < KCAT_ * NCLS_) {
        int k = idx / NCLS_, n = idx % NCLS_;
        g_Bcat1[idx] = (k < HID_) ? Ws1[k * NCLS_ + n] : Wn1[(k - HID_) * NCLS_ + n];
    }
}

// ================= compaction: find rows actually needed by layer 1 ========
__global__ void init_remap_kernel() {
    int i = blockIdx.x * blockDim.x + threadIdx.x;
    if (i < N1_) {
        g_remap[i] = (i < N2_) ? i : -1;   // dst rows keep identity position
        if (i < N2_) g_list[i] = i;
    }
    if (i == 0) g_cnt[0] = 0;
}

__global__ void mark_kernel(const int* __restrict__ nbr1) {
    int t = blockIdx.x * blockDim.x + threadIdx.x;
    if (t >= N2_ * F1_) return;
    int j = nbr1[t];
    if (j >= N2_) {
        if (atomicCAS(&g_remap[j], -1, -2) == -1) {
            int p = N2_ + atomicAdd(&g_cnt[0], 1);
            g_list[p] = j;
            g_remap[j] = p;
        }
    }
}

// ================= layer-0 gather + mean -> bf16 hi/lo (compacted) =========
__global__ __launch_bounds__(256) void gather0_kernel(
    const int* __restrict__ gids0,
    const int* __restrict__ nbr0,
    const float* __restrict__ emb) {
    int b = blockIdx.x;
    int ncount = N2_ + g_cnt[0];
    if (b >= ncount) return;
    int i = g_list[b];                 // original dst row id
    int t = threadIdx.x;

    __shared__ int sg[F0_];
    if (t < F0_) sg[t] = gids0[nbr0[i * F0_ + t]];
    __syncthreads();

    float xdst = emb[(size_t)gids0[i] * D_IN_ + t];

    float acc = 0.f;
#pragma unroll
    for (int j = 0; j < F0_; j++) acc += emb[(size_t)sg[j] * D_IN_ + t];
    acc *= (1.0f / F0_);

    __nv_bfloat16 h0 = __float2bfloat16(xdst);
    __nv_bfloat16 l0 = __float2bfloat16(xdst - __bfloat162float(h0));
    __nv_bfloat16 h1 = __float2bfloat16(acc);
    __nv_bfloat16 l1 = __float2bfloat16(acc - __bfloat162float(h1));

    size_t base = (size_t)b * KCAT_;   // write at compact position
    g_Ah[base + t] = h0;          g_Al[base + t] = l0;
    g_Ah[base + D_IN_ + t] = h1;  g_Al[base + D_IN_ + t] = l1;
}

// ================= layer-0 GEMM: fused 3-term bf16 split ===================
// One K-sweep: per 64-wide chunk load Ah,Al,Bh,Bl; issue AhBh+AhBl+AlBh MMAs.
#define SM_STAGE 65536
#define SM_TOTAL (2 * SM_STAGE)

__device__ __forceinline__ void load_chunk4(uint32_t sb, int buf,
                                            int bm, int bn, int kc, int tid) {
    uint32_t base = sb + buf * SM_STAGE;
#pragma unroll
    for (int i = 0; i < 4; i++) {
        int idx = tid + i * 256;
        // A tiles: 128 rows x 64k, 128B/row swizzled
        {
            int row = idx >> 3, c16 = idx & 7;
            size_t so = (size_t)(bm + row) * KCAT_ + kc * 64 + c16 * 8;
            uint32_t doff = row * 128 + ((c16 ^ (row & 7)) * 16);
            cp_async16(base + doff,         g_Ah + so);
            cp_async16(base + 16384 + doff, g_Al + so);
        }
        // B tiles: 64 k-rows x 128 n, 256B/row (two 128B atoms)
        {
            int k = idx >> 4, c = idx & 15;
            size_t so = (size_t)(kc * 64 + k) * HID_ + bn + c * 8;
            uint32_t doff = k * 256 + (c >> 3) * 128 + (((c & 7) ^ (k & 7)) * 16);
            cp_async16(base + 32768 + doff, g_Bh + so);
            cp_async16(base + 49152 + doff, g_Bl + so);
        }
    }
    asm volatile("cp.async.commit_group;" ::: "memory");
}

__device__ __forceinline__ void compute_chunk4(uint32_t sb, int buf, int wm,
                                               int wn, int lane,
                                               float acc[4][4][4]) {
    uint32_t As = sb + buf * SM_STAGE;
    uint32_t Al = As + 16384;
    uint32_t Bs = As + 32768;
    uint32_t Bl = As + 49152;
#pragma unroll
    for (int step = 0; step < 4; step++) {
        uint32_t ah[4][4], al[4][4], bh[2][4], bl[2][4];
#pragma unroll
        for (int mi = 0; mi < 4; mi++) {
            int row = wm + mi * 16 + (lane & 15);
            int c16 = 2 * step + (lane >> 4);
            uint32_t off = row * 128 + ((c16 ^ (row & 7)) * 16);
            LDMX4(ah[mi], As + off);
            LDMX4(al[mi], Al + off);
        }
#pragma unroll
        for (int nb = 0; nb < 2; nb++) {
            int k  = step * 16 + (lane & 15);
            int cg = ((wn + nb * 16) >> 3) + (lane >> 4);
            uint32_t off = k * 256 + (cg >> 3) * 128 + (((cg & 7) ^ (k & 7)) * 16);
            LDMX4T(bh[nb], Bs + off);
            LDMX4T(bl[nb], Bl + off);
        }
#pragma unroll
        for (int mi = 0; mi < 4; mi++)
#pragma unroll
            for (int ni = 0; ni < 4; ni++) {
                uint32_t bh0 = bh[ni >> 1][(ni & 1) * 2];
                uint32_t bh1 = bh[ni >> 1][(ni & 1) * 2 + 1];
                uint32_t bl0 = bl[ni >> 1][(ni & 1) * 2];
                uint32_t bl1 = bl[ni >> 1][(ni & 1) * 2 + 1];
                mma16816(acc[mi][ni], ah[mi], bh0, bh1);
                mma16816(acc[mi][ni], ah[mi], bl0, bl1);
                mma16816(acc[mi][ni], al[mi], bh0, bh1);
            }
    }
}

__global__ __launch_bounds__(256) void gemm0_mma_kernel(const float* __restrict__ b0) {
    extern __shared__ char smem[];
    const int bm = blockIdx.x * 128;
    {
        int ncount = N2_ + g_cnt[0];
        if (bm >= ncount) return;      // compacted early exit
    }
    const uint32_t sb = smem_u32(smem);
    const int tid  = threadIdx.x;
    const int lane = tid & 31;
    const int warp = tid >> 5;
    const int wm = (warp & 1) * 64;
    const int wn = (warp >> 1) * 32;
    const int bn = blockIdx.y * 128;

    float acc[4][4][4];
#pragma unroll
    for (int i = 0; i < 4; i++)
#pragma unroll
        for (int j = 0; j < 4; j++)
#pragma unroll
            for (int q = 0; q < 4; q++) acc[i][j][q] = 0.f;

    const int NCH = KCAT_ / 64;  // 8
    load_chunk4(sb, 0, bm, bn, 0, tid);
    load_chunk4(sb, 1, bm, bn, 1, tid);

#pragma unroll 1
    for (int cc = 0; cc < NCH; cc++) {
        if (cc + 1 < NCH) asm volatile("cp.async.wait_group 1;" ::: "memory");
        else              asm volatile("cp.async.wait_group 0;" ::: "memory");
        __syncthreads();
        compute_chunk4(sb, cc & 1, wm, wn, lane, acc);
        __syncthreads();
        if (cc + 2 < NCH) load_chunk4(sb, cc & 1, bm, bn, cc + 2, tid);
    }

    // epilogue: bias + relu -> g_H (fp32, compacted rows)
#pragma unroll
    for (int mi = 0; mi < 4; mi++) {
#pragma unroll
        for (int ni = 0; ni < 4; ni++) {
            int col = bn + wn + ni * 8 + (lane & 3) * 2;
            float bx = __ldg(&b0[col]);
            float by = __ldg(&b0[col + 1]);
            int r0 = bm + wm + mi * 16 + (lane >> 2);
            float2 v0, v1;
            v0.x = fmaxf(acc[mi][ni][0] + bx, 0.f);
            v0.y = fmaxf(acc[mi][ni][1] + by, 0.f);
            v1.x = fmaxf(acc[mi][ni][2] + bx, 0.f);
            v1.y = fmaxf(acc[mi][ni][3] + by, 0.f);
            *(float2*)&g_H[(size_t)r0 * HID_ + col]       = v0;
            *(float2*)&g_H[(size_t)(r0 + 8) * HID_ + col] = v1;
        }
    }
}

// ================= layer-1 gather + mean (via remap) =======================
__global__ __launch_bounds__(256) void gather1_kernel(const int* __restrict__ nbr1) {
    int i = blockIdx.x;   // dst row < 1024 == compact position (identity)
    int t = threadIdx.x;

    __shared__ int sp[F1_];
    if (t < F1_) sp[t] = g_remap[nbr1[i * F1_ + t]];
    __syncthreads();

    float acc = 0.f;
#pragma unroll
    for (int j = 0; j < F1_; j++) acc += g_H[(size_t)sp[j] * HID_ + t];

    g_Acat1[i * KCAT_ + t]        = g_H[(size_t)i * HID_ + t];
    g_Acat1[i * KCAT_ + HID_ + t] = acc * (1.0f / F1_);
}

// ================= layer-1 GEMM (tiny, fp32 SIMT) ==========================
__global__ __launch_bounds__(256) void out_kernel(const float* __restrict__ b1,
                                                  float* __restrict__ out) {
    int idx = blockIdx.x * blockDim.x + threadIdx.x;
    if (idx >= N2_ * NCLS_) return;
    int i = idx / NCLS_;
    int c = idx % NCLS_;

    const float* a = &g_Acat1[(size_t)i * KCAT_];
    float acc = b1[c];
#pragma unroll 8
    for (int k = 0; k < KCAT_; k++) acc += a[k] * g_Bcat1[k * NCLS_ + c];
    out[idx] = acc;
}

// ================= launch ===================================================
extern "C" void kernel_launch(void* const* d_in, const int* in_sizes, int n_in,
                              void* d_out, int out_size) {
    const int*   gids0 = (const int*)d_in[0];
    const int*   nbr0  = (const int*)d_in[1];
    const int*   nbr1  = (const int*)d_in[2];
    const float* emb   = (const float*)d_in[3];
    const float* Ws0   = (const float*)d_in[4];
    const float* Wn0   = (const float*)d_in[5];
    const float* b0    = (const float*)d_in[6];
    const float* Ws1   = (const float*)d_in[7];
    const float* Wn1   = (const float*)d_in[8];
    const float* b1    = (const float*)d_in[9];
    float* out = (float*)d_out;

    cudaFuncSetAttribute(gemm0_mma_kernel,
                         cudaFuncAttributeMaxDynamicSharedMemorySize, SM_TOTAL);

    prep_b_kernel<<<(KCAT_ * HID_ + 255) / 256, 256>>>(Ws0, Wn0, Ws1, Wn1);
    init_remap_kernel<<<(N1_ + 255) / 256, 256>>>();
    mark_kernel<<<(N2_ * F1_ + 255) / 256, 256>>>(nbr1);
    gather0_kernel<<<N1_, 256>>>(gids0, nbr0, emb);
    gemm0_mma_kernel<<<dim3(N1_ / 128, HID_ / 128), 256, SM_TOTAL>>>(b0);
    gather1_kernel<<<N2_, 256>>>(nbr1);
    out_kernel<<<(N2_ * NCLS_ + 255) / 256, 256>>>(b1, out);
}

// round 7
// speedup vs baseline: 2.0338x; 1.1240x over previous
#include <cuda_runtime.h>
#include <cuda_fp16.h>
#include <cstdint>

#define N0_   292864
#define N1_   11264
#define N2_   1024
#define F0_   25
#define F1_   10
#define D_IN_ 256
#define HID_  256
#define NCLS_ 47
#define KCAT_ 512

// ---------------- scratch (device globals; no allocation allowed) ----------
__device__ __half g_Af[N1_ * KCAT_];    // A fp16 (compacted rows)
__device__ __half g_Bf[KCAT_ * HID_];   // B fp16, [k][n]
__device__ float g_H[N1_ * HID_];       // relu(layer0), compacted rows
__device__ float g_Acat1[N2_ * KCAT_];
__device__ float g_Bcat1[KCAT_ * NCLS_];
__device__ int   g_remap[N1_];
__device__ int   g_list[N1_];
__device__ int   g_cnt[1];

// ================= helpers =================================================
__device__ __forceinline__ uint32_t smem_u32(const void* p) {
    uint32_t a;
    asm("{ .reg .u64 t; cvta.to.shared.u64 t, %1; cvt.u32.u64 %0, t; }"
        : "=r"(a) : "l"(p));
    return a;
}
__device__ __forceinline__ void cp_async16(uint32_t dst, const void* src) {
    asm volatile("cp.async.cg.shared.global [%0], [%1], 16;"
                 :: "r"(dst), "l"(src) : "memory");
}
#define LDMX4(r, a)                                                            \
    asm volatile("ldmatrix.sync.aligned.m8n8.x4.shared.b16 {%0,%1,%2,%3}, [%4];" \
        : "=r"((r)[0]), "=r"((r)[1]), "=r"((r)[2]), "=r"((r)[3]) : "r"(a))
#define LDMX4T(r, a)                                                           \
    asm volatile("ldmatrix.sync.aligned.m8n8.x4.trans.shared.b16 {%0,%1,%2,%3}, [%4];" \
        : "=r"((r)[0]), "=r"((r)[1]), "=r"((r)[2]), "=r"((r)[3]) : "r"(a))

__device__ __forceinline__ void mma16816(float* c, const uint32_t* a,
                                         uint32_t b0, uint32_t b1) {
    asm volatile(
        "mma.sync.aligned.m16n8k16.row.col.f32.f16.f16.f32 "
        "{%0,%1,%2,%3}, {%4,%5,%6,%7}, {%8,%9}, {%0,%1,%2,%3};"
        : "+f"(c[0]), "+f"(c[1]), "+f"(c[2]), "+f"(c[3])
        : "r"(a[0]), "r"(a[1]), "r"(a[2]), "r"(a[3]), "r"(b0), "r"(b1));
}

// ================= weight prep =============================================
__global__ void prep_b_kernel(const float* __restrict__ Ws0,
                              const float* __restrict__ Wn0,
                              const float* __restrict__ Ws1,
                              const float* __restrict__ Wn1) {
    int idx = blockIdx.x * blockDim.x + threadIdx.x;
    if (idx < KCAT_ * HID_) {
        int k = idx / HID_, n = idx % HID_;
        float w = (k < D_IN_) ? Ws0[k * HID_ + n] : Wn0[(k - D_IN_) * HID_ + n];
        g_Bf[idx] = __float2half(w);
    }
    if (idx < KCAT_ * NCLS_) {
        int k = idx / NCLS_, n = idx % NCLS_;
        g_Bcat1[idx] = (k < HID_) ? Ws1[k * NCLS_ + n] : Wn1[(k - HID_) * NCLS_ + n];
    }
}

// ================= compaction ==============================================
__global__ void init_remap_kernel() {
    int i = blockIdx.x * blockDim.x + threadIdx.x;
    if (i < N1_) {
        g_remap[i] = (i < N2_) ? i : -1;
        if (i < N2_) g_list[i] = i;
    }
    if (i == 0) g_cnt[0] = 0;
}

__global__ void mark_kernel(const int* __restrict__ nbr1) {
    int t = blockIdx.x * blockDim.x + threadIdx.x;
    if (t >= N2_ * F1_) return;
    int j = nbr1[t];
    if (j >= N2_) {
        if (atomicCAS(&g_remap[j], -1, -2) == -1) {
            int p = N2_ + atomicAdd(&g_cnt[0], 1);
            g_list[p] = j;
            g_remap[j] = p;
        }
    }
}

// ================= layer-0 gather + mean -> fp16 (compacted) ===============
// 4 dst rows per block; 64 threads/row; float4 (16B) loads => 26 LDG.128/thread
__global__ __launch_bounds__(256) void gather0_kernel(
    const int* __restrict__ gids0,
    const int* __restrict__ nbr0,
    const float* __restrict__ emb) {
    int tid = threadIdx.x;
    int sub = tid >> 6;            // 0..3: which dst row in this block
    int lt  = tid & 63;            // thread within row
    int b   = blockIdx.x * 4 + sub;
    int ncount = N2_ + g_cnt[0];
    bool active = (b < ncount);

    __shared__ int sg[4][F0_];
    __shared__ int sdst[4];

    int i = active ? g_list[b] : 0;
    if (active && lt < F0_) sg[sub][lt] = gids0[nbr0[i * F0_ + lt]];
    if (active && lt == 32) sdst[sub] = gids0[i];
    __syncthreads();

    if (!active) return;

    int ft = lt * 4;  // feature base (float4)
    float4 xd = *(const float4*)&emb[(size_t)sdst[sub] * D_IN_ + ft];

    float4 acc = make_float4(0.f, 0.f, 0.f, 0.f);
#pragma unroll
    for (int j = 0; j < F0_; j++) {
        float4 v = *(const float4*)&emb[(size_t)sg[sub][j] * D_IN_ + ft];
        acc.x += v.x; acc.y += v.y; acc.z += v.z; acc.w += v.w;
    }
    const float s = 1.0f / F0_;

    __half2 d01 = __floats2half2_rn(xd.x, xd.y);
    __half2 d23 = __floats2half2_rn(xd.z, xd.w);
    __half2 a01 = __floats2half2_rn(acc.x * s, acc.y * s);
    __half2 a23 = __floats2half2_rn(acc.z * s, acc.w * s);

    size_t base = (size_t)b * KCAT_;
    *(__half2*)&g_Af[base + ft]             = d01;
    *(__half2*)&g_Af[base + ft + 2]         = d23;
    *(__half2*)&g_Af[base + D_IN_ + ft]     = a01;
    *(__half2*)&g_Af[base + D_IN_ + ft + 2] = a23;
}

// ================= layer-0 GEMM: single-pass fp16 mma ======================
// CTA tile 128x128, K-chunk 64, 4-stage cp.async pipeline, 8 warps (64x32)
#define SM_STAGE 32768
#define SM_TOTAL (4 * SM_STAGE)

__device__ __forceinline__ void load_chunk(uint32_t sb, int buf,
                                           int bm, int bn, int kc, int tid) {
    uint32_t base = sb + buf * SM_STAGE;
#pragma unroll
    for (int i = 0; i < 4; i++) {
        int idx = tid + i * 256;
        // A: 128 rows x 64 k (128B/row), swizzled
        {
            int row = idx >> 3, c16 = idx & 7;
            size_t so = (size_t)(bm + row) * KCAT_ + kc * 64 + c16 * 8;
            uint32_t doff = row * 128 + ((c16 ^ (row & 7)) * 16);
            cp_async16(base + doff, g_Af + so);
        }
        // B: 64 k-rows x 128 n (256B/row, two 128B atoms)
        {
            int k = idx >> 4, c = idx & 15;
            size_t so = (size_t)(kc * 64 + k) * HID_ + bn + c * 8;
            uint32_t doff = k * 256 + (c >> 3) * 128 + (((c & 7) ^ (k & 7)) * 16);
            cp_async16(base + 16384 + doff, g_Bf + so);
        }
    }
    asm volatile("cp.async.commit_group;" ::: "memory");
}

__device__ __forceinline__ void compute_chunk(uint32_t sb, int buf, int wm,
                                              int wn, int lane,
                                              float acc[4][4][4]) {
    uint32_t As = sb + buf * SM_STAGE;
    uint32_t Bs = As + 16384;
#pragma unroll
    for (int step = 0; step < 4; step++) {
        uint32_t a[4][4], b[2][4];
#pragma unroll
        for (int mi = 0; mi < 4; mi++) {
            int row = wm + mi * 16 + (lane & 15);
            int c16 = 2 * step + (lane >> 4);
            LDMX4(a[mi], As + row * 128 + ((c16 ^ (row & 7)) * 16));
        }
#pragma unroll
        for (int nb = 0; nb < 2; nb++) {
            int k  = step * 16 + (lane & 15);
            int cg = ((wn + nb * 16) >> 3) + (lane >> 4);
            LDMX4T(b[nb], Bs + k * 256 + (cg >> 3) * 128
                         + (((cg & 7) ^ (k & 7)) * 16));
        }
#pragma unroll
        for (int mi = 0; mi < 4; mi++)
#pragma unroll
            for (int ni = 0; ni < 4; ni++)
                mma16816(acc[mi][ni], a[mi],
                         b[ni >> 1][(ni & 1) * 2],
                         b[ni >> 1][(ni & 1) * 2 + 1]);
    }
}

__global__ __launch_bounds__(256) void gemm0_mma_kernel(const float* __restrict__ b0) {
    extern __shared__ char smem[];
    const int bm = blockIdx.x * 128;
    {
        int ncount = N2_ + g_cnt[0];
        if (bm >= ncount) return;
    }
    const uint32_t sb = smem_u32(smem);
    const int tid  = threadIdx.x;
    const int lane = tid & 31;
    const int warp = tid >> 5;
    const int wm = (warp & 1) * 64;
    const int wn = (warp >> 1) * 32;
    const int bn = blockIdx.y * 128;

    float acc[4][4][4];
#pragma unroll
    for (int i = 0; i < 4; i++)
#pragma unroll
        for (int j = 0; j < 4; j++)
#pragma unroll
            for (int q = 0; q < 4; q++) acc[i][j][q] = 0.f;

    const int NCH = KCAT_ / 64;  // 8
    load_chunk(sb, 0, bm, bn, 0, tid);
    load_chunk(sb, 1, bm, bn, 1, tid);
    load_chunk(sb, 2, bm, bn, 2, tid);

#pragma unroll 1
    for (int cc = 0; cc < NCH; cc++) {
        asm volatile("cp.async.wait_group 2;" ::: "memory");
        __syncthreads();
        int nc = cc + 3;
        if (nc < NCH) load_chunk(sb, nc & 3, bm, bn, nc, tid);
        else asm volatile("cp.async.commit_group;" ::: "memory");
        compute_chunk(sb, cc & 3, wm, wn, lane, acc);
        __syncthreads();
    }

    // epilogue: bias + relu -> g_H (fp32, compacted rows)
#pragma unroll
    for (int mi = 0; mi < 4; mi++) {
#pragma unroll
        for (int ni = 0; ni < 4; ni++) {
            int col = bn + wn + ni * 8 + (lane & 3) * 2;
            float bx = __ldg(&b0[col]);
            float by = __ldg(&b0[col + 1]);
            int r0 = bm + wm + mi * 16 + (lane >> 2);
            float2 v0, v1;
            v0.x = fmaxf(acc[mi][ni][0] + bx, 0.f);
            v0.y = fmaxf(acc[mi][ni][1] + by, 0.f);
            v1.x = fmaxf(acc[mi][ni][2] + bx, 0.f);
            v1.y = fmaxf(acc[mi][ni][3] + by, 0.f);
            *(float2*)&g_H[(size_t)r0 * HID_ + col]       = v0;
            *(float2*)&g_H[(size_t)(r0 + 8) * HID_ + col] = v1;
        }
    }
}

// ================= layer-1 gather + mean (via remap) =======================
__global__ __launch_bounds__(256) void gather1_kernel(const int* __restrict__ nbr1) {
    int i = blockIdx.x;
    int t = threadIdx.x;

    __shared__ int sp[F1_];
    if (t < F1_) sp[t] = g_remap[nbr1[i * F1_ + t]];
    __syncthreads();

    float acc = 0.f;
#pragma unroll
    for (int j = 0; j < F1_; j++) acc += g_H[(size_t)sp[j] * HID_ + t];

    g_Acat1[i * KCAT_ + t]        = g_H[(size_t)i * HID_ + t];
    g_Acat1[i * KCAT_ + HID_ + t] = acc * (1.0f / F1_);
}

// ================= layer-1 GEMM (tiny, fp32 SIMT) ==========================
__global__ __launch_bounds__(256) void out_kernel(const float* __restrict__ b1,
                                                  float* __restrict__ out) {
    int idx = blockIdx.x * blockDim.x + threadIdx.x;
    if (idx >= N2_ * NCLS_) return;
    int i = idx / NCLS_;
    int c = idx % NCLS_;

    const float* a = &g_Acat1[(size_t)i * KCAT_];
    float acc = b1[c];
#pragma unroll 8
    for (int k = 0; k < KCAT_; k++) acc += a[k] * g_Bcat1[k * NCLS_ + c];
    out[idx] = acc;
}

// ================= launch ===================================================
extern "C" void kernel_launch(void* const* d_in, const int* in_sizes, int n_in,
                              void* d_out, int out_size) {
    const int*   gids0 = (const int*)d_in[0];
    const int*   nbr0  = (const int*)d_in[1];
    const int*   nbr1  = (const int*)d_in[2];
    const float* emb   = (const float*)d_in[3];
    const float* Ws0   = (const float*)d_in[4];
    const float* Wn0   = (const float*)d_in[5];
    const float* b0    = (const float*)d_in[6];
    const float* Ws1   = (const float*)d_in[7];
    const float* Wn1   = (const float*)d_in[8];
    const float* b1    = (const float*)d_in[9];
    float* out = (float*)d_out;

    cudaFuncSetAttribute(gemm0_mma_kernel,
                         cudaFuncAttributeMaxDynamicSharedMemorySize, SM_TOTAL);

    prep_b_kernel<<<(KCAT_ * HID_ + 255) / 256, 256>>>(Ws0, Wn0, Ws1, Wn1);
    init_remap_kernel<<<(N1_ + 255) / 256, 256>>>();
    mark_kernel<<<(N2_ * F1_ + 255) / 256, 256>>>(nbr1);
    gather0_kernel<<<(N1_ + 3) / 4, 256>>>(gids0, nbr0, emb);
    gemm0_mma_kernel<<<dim3(N1_ / 128, HID_ / 128), 256, SM_TOTAL>>>(b0);
    gather1_kernel<<<N2_, 256>>>(nbr1);
    out_kernel<<<(N2_ * NCLS_ + 255) / 256, 256>>>(b1, out);
}

// round 8
// speedup vs baseline: 3.8792x; 1.9073x over previous
#include <cuda_runtime.h>
#include <cuda_fp16.h>
#include <cstdint>

#define N0_   292864
#define N1_   11264
#define N2_   1024
#define F0_   25
#define F1_   10
#define D_IN_ 256
#define HID_  256
#define NCLS_ 47
#define KCAT_ 512

// ---------------- scratch (device globals; no allocation allowed) ----------
__device__ __half g_Af[N1_ * KCAT_];    // A fp16 (compacted rows)
__device__ __half g_Bf[KCAT_ * HID_];   // B fp16, [k][n]
__device__ float g_H[N1_ * HID_];       // relu(layer0), compacted rows
__device__ float g_Bcat1[KCAT_ * NCLS_];
__device__ int   g_remap[N1_];
__device__ int   g_list[N1_];
__device__ int   g_cnt[1];

// ================= helpers =================================================
__device__ __forceinline__ uint32_t smem_u32(const void* p) {
    uint32_t a;
    asm("{ .reg .u64 t; cvta.to.shared.u64 t, %1; cvt.u32.u64 %0, t; }"
        : "=r"(a) : "l"(p));
    return a;
}
__device__ __forceinline__ void cp_async16(uint32_t dst, const void* src) {
    asm volatile("cp.async.cg.shared.global [%0], [%1], 16;"
                 :: "r"(dst), "l"(src) : "memory");
}
#define LDMX4(r, a)                                                            \
    asm volatile("ldmatrix.sync.aligned.m8n8.x4.shared.b16 {%0,%1,%2,%3}, [%4];" \
        : "=r"((r)[0]), "=r"((r)[1]), "=r"((r)[2]), "=r"((r)[3]) : "r"(a))
#define LDMX4T(r, a)                                                           \
    asm volatile("ldmatrix.sync.aligned.m8n8.x4.trans.shared.b16 {%0,%1,%2,%3}, [%4];" \
        : "=r"((r)[0]), "=r"((r)[1]), "=r"((r)[2]), "=r"((r)[3]) : "r"(a))

__device__ __forceinline__ void mma16816(float* c, const uint32_t* a,
                                         uint32_t b0, uint32_t b1) {
    asm volatile(
        "mma.sync.aligned.m16n8k16.row.col.f32.f16.f16.f32 "
        "{%0,%1,%2,%3}, {%4,%5,%6,%7}, {%8,%9}, {%0,%1,%2,%3};"
        : "+f"(c[0]), "+f"(c[1]), "+f"(c[2]), "+f"(c[3])
        : "r"(a[0]), "r"(a[1]), "r"(a[2]), "r"(a[3]), "r"(b0), "r"(b1));
}

// ================= prep: weights + remap init (merged) =====================
__global__ void prep_init_kernel(const float* __restrict__ Ws0,
                                 const float* __restrict__ Wn0,
                                 const float* __restrict__ Ws1,
                                 const float* __restrict__ Wn1) {
    int idx = blockIdx.x * blockDim.x + threadIdx.x;
    if (idx < KCAT_ * HID_) {
        int k = idx / HID_, n = idx % HID_;
        float w = (k < D_IN_) ? Ws0[k * HID_ + n] : Wn0[(k - D_IN_) * HID_ + n];
        g_Bf[idx] = __float2half(w);
    }
    if (idx < KCAT_ * NCLS_) {
        int k = idx / NCLS_, n = idx % NCLS_;
        g_Bcat1[idx] = (k < HID_) ? Ws1[k * NCLS_ + n] : Wn1[(k - HID_) * NCLS_ + n];
    }
    if (idx < N1_) {
        g_remap[idx] = (idx < N2_) ? idx : -1;
        if (idx < N2_) g_list[idx] = idx;
    }
    if (idx == 0) g_cnt[0] = 0;
}

__global__ void mark_kernel(const int* __restrict__ nbr1) {
    int t = blockIdx.x * blockDim.x + threadIdx.x;
    if (t >= N2_ * F1_) return;
    int j = nbr1[t];
    if (j >= N2_) {
        if (atomicCAS(&g_remap[j], -1, -2) == -1) {
            int p = N2_ + atomicAdd(&g_cnt[0], 1);
            g_list[p] = j;
            g_remap[j] = p;
        }
    }
}

// ================= layer-0 gather + mean -> fp16 (compacted) ===============
__global__ __launch_bounds__(256) void gather0_kernel(
    const int* __restrict__ gids0,
    const int* __restrict__ nbr0,
    const float* __restrict__ emb) {
    int tid = threadIdx.x;
    int sub = tid >> 6;
    int lt  = tid & 63;
    int b   = blockIdx.x * 4 + sub;
    int ncount = N2_ + g_cnt[0];
    bool active = (b < ncount);

    __shared__ int sg[4][F0_];
    __shared__ int sdst[4];

    int i = active ? g_list[b] : 0;
    if (active && lt < F0_) sg[sub][lt] = gids0[nbr0[i * F0_ + lt]];
    if (active && lt == 32) sdst[sub] = gids0[i];
    __syncthreads();

    if (!active) return;

    int ft = lt * 4;
    float4 xd = *(const float4*)&emb[(size_t)sdst[sub] * D_IN_ + ft];

    float4 acc = make_float4(0.f, 0.f, 0.f, 0.f);
#pragma unroll
    for (int j = 0; j < F0_; j++) {
        float4 v = *(const float4*)&emb[(size_t)sg[sub][j] * D_IN_ + ft];
        acc.x += v.x; acc.y += v.y; acc.z += v.z; acc.w += v.w;
    }
    const float s = 1.0f / F0_;

    __half2 d01 = __floats2half2_rn(xd.x, xd.y);
    __half2 d23 = __floats2half2_rn(xd.z, xd.w);
    __half2 a01 = __floats2half2_rn(acc.x * s, acc.y * s);
    __half2 a23 = __floats2half2_rn(acc.z * s, acc.w * s);

    size_t base = (size_t)b * KCAT_;
    *(__half2*)&g_Af[base + ft]             = d01;
    *(__half2*)&g_Af[base + ft + 2]         = d23;
    *(__half2*)&g_Af[base + D_IN_ + ft]     = a01;
    *(__half2*)&g_Af[base + D_IN_ + ft + 2] = a23;
}

// ================= layer-0 GEMM: single-pass fp16 mma ======================
#define SM_STAGE 32768
#define SM_TOTAL (4 * SM_STAGE)

__device__ __forceinline__ void load_chunk(uint32_t sb, int buf,
                                           int bm, int bn, int kc, int tid) {
    uint32_t base = sb + buf * SM_STAGE;
#pragma unroll
    for (int i = 0; i < 4; i++) {
        int idx = tid + i * 256;
        {
            int row = idx >> 3, c16 = idx & 7;
            size_t so = (size_t)(bm + row) * KCAT_ + kc * 64 + c16 * 8;
            uint32_t doff = row * 128 + ((c16 ^ (row & 7)) * 16);
            cp_async16(base + doff, g_Af + so);
        }
        {
            int k = idx >> 4, c = idx & 15;
            size_t so = (size_t)(kc * 64 + k) * HID_ + bn + c * 8;
            uint32_t doff = k * 256 + (c >> 3) * 128 + (((c & 7) ^ (k & 7)) * 16);
            cp_async16(base + 16384 + doff, g_Bf + so);
        }
    }
    asm volatile("cp.async.commit_group;" ::: "memory");
}

__device__ __forceinline__ void compute_chunk(uint32_t sb, int buf, int wm,
                                              int wn, int lane,
                                              float acc[4][4][4]) {
    uint32_t As = sb + buf * SM_STAGE;
    uint32_t Bs = As + 16384;
#pragma unroll
    for (int step = 0; step < 4; step++) {
        uint32_t a[4][4], b[2][4];
#pragma unroll
        for (int mi = 0; mi < 4; mi++) {
            int row = wm + mi * 16 + (lane & 15);
            int c16 = 2 * step + (lane >> 4);
            LDMX4(a[mi], As + row * 128 + ((c16 ^ (row & 7)) * 16));
        }
#pragma unroll
        for (int nb = 0; nb < 2; nb++) {
            int k  = step * 16 + (lane & 15);
            int cg = ((wn + nb * 16) >> 3) + (lane >> 4);
            LDMX4T(b[nb], Bs + k * 256 + (cg >> 3) * 128
                         + (((cg & 7) ^ (k & 7)) * 16));
        }
#pragma unroll
        for (int mi = 0; mi < 4; mi++)
#pragma unroll
            for (int ni = 0; ni < 4; ni++)
                mma16816(acc[mi][ni], a[mi],
                         b[ni >> 1][(ni & 1) * 2],
                         b[ni >> 1][(ni & 1) * 2 + 1]);
    }
}

__global__ __launch_bounds__(256) void gemm0_mma_kernel(const float* __restrict__ b0) {
    extern __shared__ char smem[];
    const int bm = blockIdx.x * 128;
    {
        int ncount = N2_ + g_cnt[0];
        if (bm >= ncount) return;
    }
    const uint32_t sb = smem_u32(smem);
    const int tid  = threadIdx.x;
    const int lane = tid & 31;
    const int warp = tid >> 5;
    const int wm = (warp & 1) * 64;
    const int wn = (warp >> 1) * 32;
    const int bn = blockIdx.y * 128;

    float acc[4][4][4];
#pragma unroll
    for (int i = 0; i < 4; i++)
#pragma unroll
        for (int j = 0; j < 4; j++)
#pragma unroll
            for (int q = 0; q < 4; q++) acc[i][j][q] = 0.f;

    const int NCH = KCAT_ / 64;  // 8
    load_chunk(sb, 0, bm, bn, 0, tid);
    load_chunk(sb, 1, bm, bn, 1, tid);
    load_chunk(sb, 2, bm, bn, 2, tid);

#pragma unroll 1
    for (int cc = 0; cc < NCH; cc++) {
        asm volatile("cp.async.wait_group 2;" ::: "memory");
        __syncthreads();
        // load into buf (cc+3)&3 == (cc-1)&3: all threads finished computing
        // chunk cc-1 (guaranteed by the sync above), so overwrite is safe.
        int nc = cc + 3;
        if (nc < NCH) load_chunk(sb, nc & 3, bm, bn, nc, tid);
        else asm volatile("cp.async.commit_group;" ::: "memory");
        compute_chunk(sb, cc & 3, wm, wn, lane, acc);
    }

    // epilogue: bias + relu -> g_H (fp32, compacted rows)
#pragma unroll
    for (int mi = 0; mi < 4; mi++) {
#pragma unroll
        for (int ni = 0; ni < 4; ni++) {
            int col = bn + wn + ni * 8 + (lane & 3) * 2;
            float bx = __ldg(&b0[col]);
            float by = __ldg(&b0[col + 1]);
            int r0 = bm + wm + mi * 16 + (lane >> 2);
            float2 v0, v1;
            v0.x = fmaxf(acc[mi][ni][0] + bx, 0.f);
            v0.y = fmaxf(acc[mi][ni][1] + by, 0.f);
            v1.x = fmaxf(acc[mi][ni][2] + bx, 0.f);
            v1.y = fmaxf(acc[mi][ni][3] + by, 0.f);
            *(float2*)&g_H[(size_t)r0 * HID_ + col]       = v0;
            *(float2*)&g_H[(size_t)(r0 + 8) * HID_ + col] = v1;
        }
    }
}

// ================= fused layer-1: gather + mean + GEMM + bias ==============
// One block per dst row. Build hcat[512] in smem, then 47 classes x 4 k-chunks
// across 188 threads, smem tree-reduce. No g_Acat1 round-trip.
__global__ __launch_bounds__(256) void layer1_kernel(
    const int* __restrict__ nbr1,
    const float* __restrict__ b1,
    float* __restrict__ out) {
    int i = blockIdx.x;
    int t = threadIdx.x;

    __shared__ float hcat[KCAT_];
    __shared__ float part[4][NCLS_];
    __shared__ int sp[F1_];

    if (t < F1_) sp[t] = g_remap[nbr1[i * F1_ + t]];
    __syncthreads();

    {
        float acc = 0.f;
#pragma unroll
        for (int j = 0; j < F1_; j++) acc += g_H[(size_t)sp[j] * HID_ + t];
        hcat[t]        = g_H[(size_t)i * HID_ + t];
        hcat[HID_ + t] = acc * (1.0f / F1_);
    }
    __syncthreads();

    if (t < NCLS_ * 4) {
        int c = t % NCLS_;
        int q = t / NCLS_;
        const float* B = g_Bcat1 + c;
        float acc = 0.f;
        int k0 = q * 128;
#pragma unroll 4
        for (int k = 0; k < 128; k++)
            acc += hcat[k0 + k] * B[(size_t)(k0 + k) * NCLS_];
        part[q][c] = acc;
    }
    __syncthreads();

    if (t < NCLS_) {
        out[i * NCLS_ + t] = b1[t] + ((part[0][t] + part[1][t])
                                    + (part[2][t] + part[3][t]));
    }
}

// ================= launch ===================================================
extern "C" void kernel_launch(void* const* d_in, const int* in_sizes, int n_in,
                              void* d_out, int out_size) {
    const int*   gids0 = (const int*)d_in[0];
    const int*   nbr0  = (const int*)d_in[1];
    const int*   nbr1  = (const int*)d_in[2];
    const float* emb   = (const float*)d_in[3];
    const float* Ws0   = (const float*)d_in[4];
    const float* Wn0   = (const float*)d_in[5];
    const float* b0    = (const float*)d_in[6];
    const float* Ws1   = (const float*)d_in[7];
    const float* Wn1   = (const float*)d_in[8];
    const float* b1    = (const float*)d_in[9];
    float* out = (float*)d_out;

    cudaFuncSetAttribute(gemm0_mma_kernel,
                         cudaFuncAttributeMaxDynamicSharedMemorySize, SM_TOTAL);

    prep_init_kernel<<<(KCAT_ * HID_ + 255) / 256, 256>>>(Ws0, Wn0, Ws1, Wn1);
    mark_kernel<<<(N2_ * F1_ + 255) / 256, 256>>>(nbr1);
    gather0_kernel<<<(N1_ + 3) / 4, 256>>>(gids0, nbr0, emb);
    gemm0_mma_kernel<<<dim3(N1_ / 128, HID_ / 128), 256, SM_TOTAL>>>(b0);
    layer1_kernel<<<N2_, 256>>>(nbr1, b1, out);
}